// round 1
// baseline (speedup 1.0000x reference)
#include <cuda_runtime.h>
#include <cstdint>
#include <cstddef>

// ---------------------------------------------------------------------------
// Problem constants
// ---------------------------------------------------------------------------
#define BB      8
#define LL      1024
#define DM      512
#define DI      1024
#define NSTATE  16
#define RK      32
#define NT      (BB*LL)          // 8192 tokens
#define DEPTH   4

// ---------------------------------------------------------------------------
// Scratch buffers (device globals; allocation-free per harness rules)
// ---------------------------------------------------------------------------
__device__ float g_resid[NT*DM];          // residual stream
__device__ float g_hid  [NT*DM];          // layer output (hidden)
__device__ float g_h    [NT*DM];          // layernormed input
__device__ float g_xz   [NT*2*DI];        // in_proj output (xc | z)
__device__ float g_xc   [2*NT*DI];        // conv+silu output, per dir
__device__ float g_xdbl [2*NT*64];        // x_proj output (dt_r|B|C)
__device__ float g_dt   [2*NT*DI];        // softplus dt
__device__ float g_y    [2*NT*DI];        // scan output (gated)
__device__ float g_o    [2*NT*DM];        // out_proj output per dir

// ---------------------------------------------------------------------------
// Helpers
// ---------------------------------------------------------------------------
__device__ __forceinline__ float warpReduceSum(float v){
#pragma unroll
    for (int o=16;o>0;o>>=1) v += __shfl_xor_sync(0xffffffffu, v, o);
    return v;
}
__device__ __forceinline__ float silu_fast(float x){
    return x / (1.f + __expf(-x));
}

// ---------------------------------------------------------------------------
// LayerNorm (+ residual update).  One block per token row (512 floats).
// src0 = x (layer 0) or resid; src1 = hidden (layers > 0) or nullptr.
// Writes updated residual and normed output.
// ---------------------------------------------------------------------------
__global__ void __launch_bounds__(128) ln_kernel(
    const float* __restrict__ src0, const float* __restrict__ src1,
    float* __restrict__ resid,
    const float* __restrict__ w, const float* __restrict__ b,
    float* __restrict__ hout)
{
    __shared__ float sm[8];
    const int row = blockIdx.x, tid = threadIdx.x;
    float4 v = reinterpret_cast<const float4*>(src0 + (size_t)row*DM)[tid];
    if (src1){
        float4 u = reinterpret_cast<const float4*>(src1 + (size_t)row*DM)[tid];
        v.x+=u.x; v.y+=u.y; v.z+=u.z; v.w+=u.w;
    }
    reinterpret_cast<float4*>(resid + (size_t)row*DM)[tid] = v;

    float s = v.x+v.y+v.z+v.w;
    s = warpReduceSum(s);
    const int wid = tid>>5, lane = tid&31;
    if (lane==0) sm[wid]=s;
    __syncthreads();
    const float mu = (sm[0]+sm[1]+sm[2]+sm[3]) * (1.f/(float)DM);
    const float dx=v.x-mu, dy=v.y-mu, dz=v.z-mu, dw=v.w-mu;
    float q = dx*dx+dy*dy+dz*dz+dw*dw;
    q = warpReduceSum(q);
    if (lane==0) sm[4+wid]=q;
    __syncthreads();
    const float var = (sm[4]+sm[5]+sm[6]+sm[7]) * (1.f/(float)DM);
    const float rs = rsqrtf(var + 1e-5f);
    const float4 wv = reinterpret_cast<const float4*>(w)[tid];
    const float4 bv = reinterpret_cast<const float4*>(b)[tid];
    float4 o;
    o.x = dx*rs*wv.x + bv.x;
    o.y = dy*rs*wv.y + bv.y;
    o.z = dz*rs*wv.z + bv.z;
    o.w = dw*rs*wv.w + bv.w;
    reinterpret_cast<float4*>(hout + (size_t)row*DM)[tid] = o;
}

// ---------------------------------------------------------------------------
// Templated SGEMM: C[M,N] = A[M,K] (lda) * W[N,K]^T  (W row-major, ld=K)
// EPI: 0 = none, 1 = softplus(x + bias[n])
// Requires M%BM==0, N%BN==0, K%BK==0 (true for all uses here).
// 256 threads/block.
// ---------------------------------------------------------------------------
template<int BM,int BN,int BK,int TM,int TN,int EPI>
__global__ void __launch_bounds__(256) gemm_kernel(
    const float* __restrict__ A, int lda,
    const float* __restrict__ W,
    const float* __restrict__ bias,
    float* __restrict__ C, int ldc,
    int K)
{
    static_assert((BM/TM)*(BN/TN) == 256, "thread layout");
    static_assert(BM*BK % 1024 == 0 && BN*BK % 1024 == 0, "tile loads");
    __shared__ float As[BK][BM];
    __shared__ float Bs[BK][BN];

    const int tid = threadIdx.x;
    const int m0 = blockIdx.y * BM;
    const int n0 = blockIdx.x * BN;
    const int tx = tid % (BN / TN);
    const int ty = tid / (BN / TN);

    float acc[TM][TN];
#pragma unroll
    for (int i=0;i<TM;i++)
#pragma unroll
        for (int j=0;j<TN;j++) acc[i][j]=0.f;

    constexpr int APER = BM*BK/1024;
    constexpr int WPER = BN*BK/1024;
    constexpr int KQ   = BK/4;

    for (int k0=0;k0<K;k0+=BK){
#pragma unroll
        for (int u=0;u<APER;u++){
            const int s = tid + u*256;
            const int r = s / KQ, kq = s % KQ;
            float4 v = *reinterpret_cast<const float4*>(A + (size_t)(m0+r)*lda + k0 + kq*4);
            As[kq*4+0][r]=v.x; As[kq*4+1][r]=v.y; As[kq*4+2][r]=v.z; As[kq*4+3][r]=v.w;
        }
#pragma unroll
        for (int u=0;u<WPER;u++){
            const int s = tid + u*256;
            const int r = s / KQ, kq = s % KQ;
            float4 v = *reinterpret_cast<const float4*>(W + (size_t)(n0+r)*K + k0 + kq*4);
            Bs[kq*4+0][r]=v.x; Bs[kq*4+1][r]=v.y; Bs[kq*4+2][r]=v.z; Bs[kq*4+3][r]=v.w;
        }
        __syncthreads();
#pragma unroll
        for (int k=0;k<BK;k++){
            float a[TM], bv[TN];
#pragma unroll
            for (int i=0;i<TM;i+=4){
                float4 t4 = *reinterpret_cast<const float4*>(&As[k][ty*TM+i]);
                a[i]=t4.x; a[i+1]=t4.y; a[i+2]=t4.z; a[i+3]=t4.w;
            }
#pragma unroll
            for (int j=0;j<TN;j+=4){
                float4 t4 = *reinterpret_cast<const float4*>(&Bs[k][tx*TN+j]);
                bv[j]=t4.x; bv[j+1]=t4.y; bv[j+2]=t4.z; bv[j+3]=t4.w;
            }
#pragma unroll
            for (int i=0;i<TM;i++)
#pragma unroll
                for (int j=0;j<TN;j++)
                    acc[i][j] += a[i]*bv[j];
        }
        __syncthreads();
    }

#pragma unroll
    for (int i=0;i<TM;i++){
        const int m = m0 + ty*TM + i;
#pragma unroll
        for (int j=0;j<TN;j+=4){
            const int n = n0 + tx*TN + j;
            float4 o;
            float* po = &o.x;
#pragma unroll
            for (int jj=0;jj<4;jj++){
                float v = acc[i][j+jj];
                if (EPI==1){
                    v += bias[n+jj];
                    v = (v > 20.f) ? v : log1pf(expf(v));
                }
                po[jj] = v;
            }
            *reinterpret_cast<float4*>(C + (size_t)m*ldc + n) = o;
        }
    }
}

// ---------------------------------------------------------------------------
// Depthwise causal conv (k=4) + bias + silu, both directions.
// dir=1 reads the time-flipped sequence; its output lives in flipped time.
// ---------------------------------------------------------------------------
__global__ void __launch_bounds__(256) conv_kernel(
    const float* __restrict__ xz,
    const float* __restrict__ cw, const float* __restrict__ cb,
    float* __restrict__ xc)
{
    const int flat = blockIdx.x*256 + threadIdx.x;     // < 2*NT*DI
    const int d   = flat & (DI-1);
    const int t   = (flat >> 10) & (LL-1);
    const int b   = (flat >> 20) & (BB-1);
    const int dir = flat >> 23;

    float acc = cb[d];
    const float w0=cw[d*4+0], w1=cw[d*4+1], w2=cw[d*4+2], w3=cw[d*4+3];
    const float* src = xz + ((size_t)b*LL)*(2*DI) + d;
#pragma unroll
    for (int j=0;j<4;j++){
        const int tt = t - 3 + j;
        if (tt >= 0){
            const int st = dir ? (LL-1-tt) : tt;
            const float wj = (j==0)?w0:(j==1)?w1:(j==2)?w2:w3;
            acc += wj * src[(size_t)st*(2*DI)];
        }
    }
    acc = silu_fast(acc);
    xc[(size_t)dir*NT*DI + ((size_t)(b*LL+t))*DI + d] = acc;
}

// ---------------------------------------------------------------------------
// Selective scan + D skip + silu(z) gating.
// Grid: 2 dirs * 8 batch * 8 d-chunks = 128 blocks, 128 threads (one per d).
// Operands are staged into smem in 16-step tiles so the recurrence never
// waits on global memory.
// ---------------------------------------------------------------------------
#define TTILE 16
__global__ void __launch_bounds__(128) scan_kernel(
    const float* __restrict__ xc,   const float* __restrict__ xdbl,
    const float* __restrict__ dt,   const float* __restrict__ xz,
    const float* __restrict__ A_log,const float* __restrict__ Dp,
    float* __restrict__ yout)
{
    __shared__ float su [TTILE][128];
    __shared__ float sdt[TTILE][128];
    __shared__ float sz [TTILE][128];
    __shared__ float sBC[TTILE][32];

    const int bx  = blockIdx.x;
    const int dir = bx >> 6;
    const int b   = (bx >> 3) & 7;
    const int dch = bx & 7;
    const int tid = threadIdx.x;
    const int d   = dch*128 + tid;

    float a[NSTATE], h[NSTATE];
#pragma unroll
    for (int n=0;n<NSTATE;n++){ a[n] = -expf(A_log[(size_t)d*NSTATE + n]); h[n]=0.f; }
    const float Dv = Dp[d];

    const size_t cb = (size_t)dir*NT*DI + (size_t)(b*LL)*DI + d;
    const float* xcp = xc + cb;
    const float* dtp = dt + cb;
    float*       yp  = yout + cb;
    const float* xdp = xdbl + ((size_t)dir*NT + (size_t)b*LL)*64 + 32;  // cols 32..63 = B|C
    const float* zp  = xz + (size_t)(b*LL)*(2*DI) + DI + d;

    const int bcrow = tid >> 3, bccq = tid & 7;

    for (int t0=0; t0<LL; t0+=TTILE){
        __syncthreads();
#pragma unroll
        for (int i=0;i<TTILE;i++){
            const int t = t0 + i;
            su [i][tid] = xcp[(size_t)t*DI];
            sdt[i][tid] = dtp[(size_t)t*DI];
            const int zt = dir ? (LL-1-t) : t;
            sz [i][tid] = zp[(size_t)zt*(2*DI)];
        }
        {
            float4 v = *reinterpret_cast<const float4*>(xdp + (size_t)(t0+bcrow)*64 + bccq*4);
            sBC[bcrow][bccq*4+0]=v.x; sBC[bcrow][bccq*4+1]=v.y;
            sBC[bcrow][bccq*4+2]=v.z; sBC[bcrow][bccq*4+3]=v.w;
        }
        __syncthreads();
#pragma unroll
        for (int i=0;i<TTILE;i++){
            const float u   = su [i][tid];
            const float dtv = sdt[i][tid];
            const float dtu = dtv * u;
            float y = u * Dv;
#pragma unroll
            for (int n=0;n<NSTATE;n++){
                const float dA = __expf(dtv * a[n]);
                h[n] = dA*h[n] + dtu * sBC[i][n];
                y   += h[n] * sBC[i][16+n];
            }
            y *= silu_fast(sz[i][tid]);
            yp[(size_t)(t0+i)*DI] = y;
        }
    }
}

// ---------------------------------------------------------------------------
// hidden[b,t,:] = o_fwd[b,t,:] + o_bwd[b,L-1-t,:]
// ---------------------------------------------------------------------------
__global__ void __launch_bounds__(256) add_kernel(
    const float* __restrict__ o, float* __restrict__ dst)
{
    const int flat = blockIdx.x*256 + threadIdx.x;   // < NT*DM
    const int e = flat & (DM-1);
    const int t = (flat >> 9) & (LL-1);
    const int b = flat >> 19;
    const int tok  = b*LL + t;
    const int tokb = b*LL + (LL-1-t);
    dst[flat] = o[(size_t)tok*DM + e] + o[(size_t)(NT + tokb)*DM + e];
}

// ---------------------------------------------------------------------------
// Launch
// ---------------------------------------------------------------------------
extern "C" void kernel_launch(void* const* d_in, const int* in_sizes, int n_in,
                              void* d_out, int out_size)
{
    (void)in_sizes; (void)n_in; (void)out_size;
    const float* x      = (const float*)d_in[0];
    const float* norm_w = (const float*)d_in[1];
    const float* norm_b = (const float*)d_in[2];
    const float* in_w   = (const float*)d_in[3];
    const float* conv_w = (const float*)d_in[4];
    const float* conv_b = (const float*)d_in[5];
    const float* xp_w   = (const float*)d_in[6];
    const float* dtp_w  = (const float*)d_in[7];
    const float* dtp_b  = (const float*)d_in[8];
    const float* A_log  = (const float*)d_in[9];
    const float* Dp     = (const float*)d_in[10];
    const float* out_w  = (const float*)d_in[11];
    float* dout = (float*)d_out;

    float *resid,*hid,*hbuf,*xz,*xc,*xdbl,*dtb,*yb,*ob;
    cudaGetSymbolAddress((void**)&resid, g_resid);
    cudaGetSymbolAddress((void**)&hid,   g_hid);
    cudaGetSymbolAddress((void**)&hbuf,  g_h);
    cudaGetSymbolAddress((void**)&xz,    g_xz);
    cudaGetSymbolAddress((void**)&xc,    g_xc);
    cudaGetSymbolAddress((void**)&xdbl,  g_xdbl);
    cudaGetSymbolAddress((void**)&dtb,   g_dt);
    cudaGetSymbolAddress((void**)&yb,    g_y);
    cudaGetSymbolAddress((void**)&ob,    g_o);

    for (int i=0;i<DEPTH;i++){
        // residual update + layernorm
        ln_kernel<<<NT,128>>>( (i==0)? x : resid, (i==0)? (const float*)nullptr : hid,
                               resid, norm_w + i*DM, norm_b + i*DM, hbuf );

        // GEMM1: xz[8192,2048] = h[8192,512] @ in_w^T
        gemm_kernel<128,128,16,8,8,0><<<dim3(2048/128, 8192/128),256>>>(
            hbuf, DM, in_w + (size_t)i*2*DI*DM, nullptr, xz, 2*DI, DM);

        // depthwise conv + silu (both directions)
        conv_kernel<<<(2*NT*DI)/256,256>>>(xz, conv_w + i*DI*4, conv_b + i*DI, xc);

        // GEMM2: xdbl[16384,64] = xc[16384,1024] @ xp_w^T
        gemm_kernel<128,64,16,8,4,0><<<dim3(64/64, 16384/128),256>>>(
            xc, DI, xp_w + (size_t)i*64*DI, nullptr, xdbl, 64, DI);

        // GEMM3: dt[16384,1024] = softplus(xdbl[:, :32] @ dtp_w^T + dtp_b)
        gemm_kernel<128,128,16,8,8,1><<<dim3(1024/128, 16384/128),256>>>(
            xdbl, 64, dtp_w + (size_t)i*DI*RK, dtp_b + i*DI, dtb, DI, RK);

        // selective scan + D skip + gating
        scan_kernel<<<128,128>>>(xc, xdbl, dtb, xz,
                                 A_log + (size_t)i*DI*NSTATE, Dp + i*DI, yb);

        // GEMM4: o[16384,512] = y[16384,1024] @ out_w^T
        gemm_kernel<128,128,16,8,8,0><<<dim3(512/128, 16384/128),256>>>(
            yb, DI, out_w + (size_t)i*DM*DI, nullptr, ob, DM, DI);

        // hidden = o_fwd + flip(o_bwd); last layer writes d_out
        add_kernel<<<(NT*DM)/256,256>>>(ob, (i==DEPTH-1)? dout : hid);
    }
}

// round 3
// speedup vs baseline: 1.9484x; 1.9484x over previous
#include <cuda_runtime.h>
#include <cuda_bf16.h>
#include <cstdint>
#include <cstddef>

// ---------------------------------------------------------------------------
// Problem constants
// ---------------------------------------------------------------------------
#define BB      8
#define LL      1024
#define DM      512
#define DI      1024
#define NSTATE  16
#define RK      32
#define NT      (BB*LL)          // 8192 tokens
#define DEPTH   4

// ---------------------------------------------------------------------------
// Scratch buffers
// ---------------------------------------------------------------------------
__device__ float g_resid[NT*DM];
__device__ float g_hid  [NT*DM];
__device__ float g_h    [NT*DM];
__device__ float g_xz   [NT*2*DI];
__device__ float g_xc   [2*NT*DI];
__device__ float g_xdbl [2*NT*64];
__device__ float g_dt   [2*NT*DI];
__device__ float g_y    [2*NT*DI];
__device__ float g_o    [2*NT*DM];

// ---------------------------------------------------------------------------
// Helpers
// ---------------------------------------------------------------------------
__device__ __forceinline__ uint32_t smem_u32(const void* p){
    uint32_t a;
    asm("{ .reg .u64 t; cvta.to.shared.u64 t, %1; cvt.u32.u64 %0, t; }" : "=r"(a) : "l"(p));
    return a;
}
__device__ __forceinline__ float warpReduceSum(float v){
#pragma unroll
    for (int o=16;o>0;o>>=1) v += __shfl_xor_sync(0xffffffffu, v, o);
    return v;
}
__device__ __forceinline__ float silu_fast(float x){
    return x / (1.f + __expf(-x));
}

__device__ __forceinline__ void ldm_x4(uint32_t* r, uint32_t addr){
    asm volatile("ldmatrix.sync.aligned.m8n8.x4.shared.b16 {%0,%1,%2,%3}, [%4];"
        : "=r"(r[0]), "=r"(r[1]), "=r"(r[2]), "=r"(r[3]) : "r"(addr));
}
__device__ __forceinline__ void mma_bf16(float* c, const uint32_t* a, const uint32_t* b){
    asm volatile(
        "mma.sync.aligned.m16n8k16.row.col.f32.bf16.bf16.f32 "
        "{%0,%1,%2,%3}, {%4,%5,%6,%7}, {%8,%9}, {%0,%1,%2,%3};"
        : "+f"(c[0]), "+f"(c[1]), "+f"(c[2]), "+f"(c[3])
        : "r"(a[0]), "r"(a[1]), "r"(a[2]), "r"(a[3]), "r"(b[0]), "r"(b[1]));
}

// fp32x4 -> (hi,lo) bf16x4, stored into 80B-pitch smem rows
__device__ __forceinline__ void cvt_store80(char* hi_base, char* lo_base,
                                            int r, int q, float4 v){
    __nv_bfloat162 h0 = __floats2bfloat162_rn(v.x, v.y);
    __nv_bfloat162 h1 = __floats2bfloat162_rn(v.z, v.w);
    float2 f0 = __bfloat1622float2(h0);
    float2 f1 = __bfloat1622float2(h1);
    __nv_bfloat162 l0 = __floats2bfloat162_rn(v.x - f0.x, v.y - f0.y);
    __nv_bfloat162 l1 = __floats2bfloat162_rn(v.z - f1.x, v.w - f1.y);
    const int off = r*80 + q*8;
    uint2 hw, lw;
    hw.x = *reinterpret_cast<uint32_t*>(&h0); hw.y = *reinterpret_cast<uint32_t*>(&h1);
    lw.x = *reinterpret_cast<uint32_t*>(&l0); lw.y = *reinterpret_cast<uint32_t*>(&l1);
    *reinterpret_cast<uint2*>(hi_base + off) = hw;
    *reinterpret_cast<uint2*>(lo_base + off) = lw;
}

// ---------------------------------------------------------------------------
// LayerNorm (+ residual update)
// ---------------------------------------------------------------------------
__global__ void __launch_bounds__(128) ln_kernel(
    const float* __restrict__ src0, const float* __restrict__ src1,
    float* __restrict__ resid,
    const float* __restrict__ w, const float* __restrict__ b,
    float* __restrict__ hout)
{
    __shared__ float sm[8];
    const int row = blockIdx.x, tid = threadIdx.x;
    float4 v = reinterpret_cast<const float4*>(src0 + (size_t)row*DM)[tid];
    if (src1){
        float4 u = reinterpret_cast<const float4*>(src1 + (size_t)row*DM)[tid];
        v.x+=u.x; v.y+=u.y; v.z+=u.z; v.w+=u.w;
    }
    reinterpret_cast<float4*>(resid + (size_t)row*DM)[tid] = v;

    float s = v.x+v.y+v.z+v.w;
    s = warpReduceSum(s);
    const int wid = tid>>5, lane = tid&31;
    if (lane==0) sm[wid]=s;
    __syncthreads();
    const float mu = (sm[0]+sm[1]+sm[2]+sm[3]) * (1.f/(float)DM);
    const float dx=v.x-mu, dy=v.y-mu, dz=v.z-mu, dw=v.w-mu;
    float q = dx*dx+dy*dy+dz*dz+dw*dw;
    q = warpReduceSum(q);
    if (lane==0) sm[4+wid]=q;
    __syncthreads();
    const float var = (sm[4]+sm[5]+sm[6]+sm[7]) * (1.f/(float)DM);
    const float rs = rsqrtf(var + 1e-5f);
    const float4 wv = reinterpret_cast<const float4*>(w)[tid];
    const float4 bv = reinterpret_cast<const float4*>(b)[tid];
    float4 o;
    o.x = dx*rs*wv.x + bv.x;
    o.y = dy*rs*wv.y + bv.y;
    o.z = dz*rs*wv.z + bv.z;
    o.w = dw*rs*wv.w + bv.w;
    reinterpret_cast<float4*>(hout + (size_t)row*DM)[tid] = o;
}

// ---------------------------------------------------------------------------
// Split-bf16 MMA GEMM (mma.sync, valid on base sm_103 target)
// C[M,N] = A[M,K] * W[N,K]^T  (fp32 in/out; 3-term hi/lo bf16 decomposition)
// BM=128, BK=32, 256 threads. BN=128 -> warp grid 2x4 (64x32 per warp);
// BN=64  -> warp grid 4x2 (32x32 per warp). Row pitch 80B => conflict-free
// ldmatrix (80 mod 128 walks all eight 16B granules across 8 rows).
// ---------------------------------------------------------------------------
template<int BN>
__global__ void __launch_bounds__(256) gemm_mma_kernel(
    const float* __restrict__ A, int lda,
    const float* __restrict__ W, int K,
    float* __restrict__ C, int ldc)
{
    constexpr int WGN = (BN==128) ? 4 : 2;
    constexpr int WGM = 8/WGN;
    constexpr int WM  = 128/WGM;        // 64 or 32
    constexpr int WN  = BN/WGN;         // 32
    constexpr int MT  = WM/16;          // 4 or 2
    constexpr int NTL = WN/8;           // 4
    constexpr int AHI = 0;
    constexpr int ALO = 128*80;
    constexpr int BHI = 2*128*80;
    constexpr int BLO = BHI + BN*80;

    __shared__ alignas(128) char smem[BHI + 2*BN*80];
    const uint32_t sb = smem_u32(smem);

    const int tid  = threadIdx.x;
    const int wid  = tid>>5, lane = tid&31;
    const int m0   = blockIdx.y*128, n0 = blockIdx.x*BN;
    const int wm0  = (wid/WGN)*WM;
    const int wn0  = (wid%WGN)*WN;

    float acc[MT][NTL][4];
#pragma unroll
    for (int i=0;i<MT;i++)
#pragma unroll
        for (int j=0;j<NTL;j++)
#pragma unroll
            for (int q=0;q<4;q++) acc[i][j][q]=0.f;

    // per-lane ldmatrix source rows
    const int a_row = (lane&7) + ((lane>>3)&1)*8;
    const int a_kb  = (lane>>4)*16;
    const int b_row = (lane&7) + (lane>>4)*8;
    const int b_kb  = ((lane>>3)&1)*16;

    for (int k0=0; k0<K; k0+=32){
        __syncthreads();
        // A tile: 128 rows x 32 K (fp32 -> hi/lo bf16)
#pragma unroll
        for (int u=0;u<4;u++){
            const int flat = tid + u*256;
            const int r = flat>>3, q = flat&7;
            float4 v = *reinterpret_cast<const float4*>(A + (size_t)(m0+r)*lda + k0 + q*4);
            cvt_store80(smem + AHI, smem + ALO, r, q, v);
        }
        // B tile: BN rows x 32 K
#pragma unroll
        for (int u=0;u<BN/32;u++){
            const int flat = tid + u*256;
            const int r = flat>>3, q = flat&7;
            float4 v = *reinterpret_cast<const float4*>(W + (size_t)(n0+r)*K + k0 + q*4);
            cvt_store80(smem + BHI, smem + BLO, r, q, v);
        }
        __syncthreads();

#pragma unroll
        for (int ks=0; ks<2; ++ks){
            uint32_t ah[MT][4], al[MT][4];
#pragma unroll
            for (int mt=0; mt<MT; ++mt){
                const uint32_t ra = (uint32_t)((wm0 + mt*16 + a_row)*80 + ks*32 + a_kb);
                ldm_x4(ah[mt], sb + AHI + ra);
                ldm_x4(al[mt], sb + ALO + ra);
            }
            uint32_t bh[NTL][2], bl[NTL][2];
#pragma unroll
            for (int tp=0; tp<NTL/2; ++tp){
                const uint32_t rb = (uint32_t)((wn0 + tp*16 + b_row)*80 + ks*32 + b_kb);
                uint32_t t4[4];
                ldm_x4(t4, sb + BHI + rb);
                bh[tp*2][0]=t4[0]; bh[tp*2][1]=t4[1]; bh[tp*2+1][0]=t4[2]; bh[tp*2+1][1]=t4[3];
                ldm_x4(t4, sb + BLO + rb);
                bl[tp*2][0]=t4[0]; bl[tp*2][1]=t4[1]; bl[tp*2+1][0]=t4[2]; bl[tp*2+1][1]=t4[3];
            }
#pragma unroll
            for (int mt=0; mt<MT; ++mt)
#pragma unroll
                for (int nt=0; nt<NTL; ++nt){
                    mma_bf16(acc[mt][nt], ah[mt], bh[nt]);
                    mma_bf16(acc[mt][nt], ah[mt], bl[nt]);
                    mma_bf16(acc[mt][nt], al[mt], bh[nt]);
                }
        }
    }

    // Epilogue: direct float2 stores from the mma C-fragment layout
    const int cr = lane>>2;           // row within 16x8 tile (0..7)
    const int cc = (lane&3)*2;        // col pair
#pragma unroll
    for (int mt=0; mt<MT; ++mt){
        const int rbase = m0 + wm0 + mt*16 + cr;
#pragma unroll
        for (int nt=0; nt<NTL; ++nt){
            const int col = n0 + wn0 + nt*8 + cc;
            float2 v0; v0.x = acc[mt][nt][0]; v0.y = acc[mt][nt][1];
            float2 v1; v1.x = acc[mt][nt][2]; v1.y = acc[mt][nt][3];
            *reinterpret_cast<float2*>(C + (size_t)rbase*ldc + col)     = v0;
            *reinterpret_cast<float2*>(C + (size_t)(rbase+8)*ldc + col) = v1;
        }
    }
}

// ---------------------------------------------------------------------------
// SIMT GEMM (GEMM3 only: K=32, softplus epilogue)
// ---------------------------------------------------------------------------
template<int BM,int BN,int BK,int TM,int TN,int EPI>
__global__ void __launch_bounds__(256) gemm_kernel(
    const float* __restrict__ A, int lda,
    const float* __restrict__ W,
    const float* __restrict__ bias,
    float* __restrict__ C, int ldc,
    int K)
{
    static_assert((BM/TM)*(BN/TN) == 256, "thread layout");
    __shared__ float As[BK][BM];
    __shared__ float Bs[BK][BN];

    const int tid = threadIdx.x;
    const int m0 = blockIdx.y * BM;
    const int n0 = blockIdx.x * BN;
    const int tx = tid % (BN / TN);
    const int ty = tid / (BN / TN);

    float acc[TM][TN];
#pragma unroll
    for (int i=0;i<TM;i++)
#pragma unroll
        for (int j=0;j<TN;j++) acc[i][j]=0.f;

    constexpr int APER = BM*BK/1024;
    constexpr int WPER = BN*BK/1024;
    constexpr int KQ   = BK/4;

    for (int k0=0;k0<K;k0+=BK){
#pragma unroll
        for (int u=0;u<APER;u++){
            const int s = tid + u*256;
            const int r = s / KQ, kq = s % KQ;
            float4 v = *reinterpret_cast<const float4*>(A + (size_t)(m0+r)*lda + k0 + kq*4);
            As[kq*4+0][r]=v.x; As[kq*4+1][r]=v.y; As[kq*4+2][r]=v.z; As[kq*4+3][r]=v.w;
        }
#pragma unroll
        for (int u=0;u<WPER;u++){
            const int s = tid + u*256;
            const int r = s / KQ, kq = s % KQ;
            float4 v = *reinterpret_cast<const float4*>(W + (size_t)(n0+r)*K + k0 + kq*4);
            Bs[kq*4+0][r]=v.x; Bs[kq*4+1][r]=v.y; Bs[kq*4+2][r]=v.z; Bs[kq*4+3][r]=v.w;
        }
        __syncthreads();
#pragma unroll
        for (int k=0;k<BK;k++){
            float a[TM], bv[TN];
#pragma unroll
            for (int i=0;i<TM;i+=4){
                float4 t4 = *reinterpret_cast<const float4*>(&As[k][ty*TM+i]);
                a[i]=t4.x; a[i+1]=t4.y; a[i+2]=t4.z; a[i+3]=t4.w;
            }
#pragma unroll
            for (int j=0;j<TN;j+=4){
                float4 t4 = *reinterpret_cast<const float4*>(&Bs[k][tx*TN+j]);
                bv[j]=t4.x; bv[j+1]=t4.y; bv[j+2]=t4.z; bv[j+3]=t4.w;
            }
#pragma unroll
            for (int i=0;i<TM;i++)
#pragma unroll
                for (int j=0;j<TN;j++)
                    acc[i][j] += a[i]*bv[j];
        }
        __syncthreads();
    }

#pragma unroll
    for (int i=0;i<TM;i++){
        const int m = m0 + ty*TM + i;
#pragma unroll
        for (int j=0;j<TN;j+=4){
            const int n = n0 + tx*TN + j;
            float4 o;
            float* po = &o.x;
#pragma unroll
            for (int jj=0;jj<4;jj++){
                float v = acc[i][j+jj];
                if (EPI==1){
                    v += bias[n+jj];
                    v = (v > 20.f) ? v : log1pf(__expf(v));
                }
                po[jj] = v;
            }
            *reinterpret_cast<float4*>(C + (size_t)m*ldc + n) = o;
        }
    }
}

// ---------------------------------------------------------------------------
// Depthwise causal conv (k=4) + bias + silu, both directions.
// ---------------------------------------------------------------------------
__global__ void __launch_bounds__(256) conv_kernel(
    const float* __restrict__ xz,
    const float* __restrict__ cw, const float* __restrict__ cb,
    float* __restrict__ xc)
{
    const int flat = blockIdx.x*256 + threadIdx.x;
    const int d   = flat & (DI-1);
    const int t   = (flat >> 10) & (LL-1);
    const int b   = (flat >> 20) & (BB-1);
    const int dir = flat >> 23;

    float acc = cb[d];
    const float w0=cw[d*4+0], w1=cw[d*4+1], w2=cw[d*4+2], w3=cw[d*4+3];
    const float* src = xz + ((size_t)b*LL)*(2*DI) + d;
#pragma unroll
    for (int j=0;j<4;j++){
        const int tt = t - 3 + j;
        if (tt >= 0){
            const int st = dir ? (LL-1-tt) : tt;
            const float wj = (j==0)?w0:(j==1)?w1:(j==2)?w2:w3;
            acc += wj * src[(size_t)st*(2*DI)];
        }
    }
    acc = silu_fast(acc);
    xc[(size_t)dir*NT*DI + ((size_t)(b*LL+t))*DI + d] = acc;
}

// ---------------------------------------------------------------------------
// Selective scan + D skip + silu(z) gating (fast power-chain path when
// A rows are multiples of A[...,0], true for this model).
// ---------------------------------------------------------------------------
#define TTILE 16
__global__ void __launch_bounds__(128) scan_kernel(
    const float* __restrict__ xc,   const float* __restrict__ xdbl,
    const float* __restrict__ dt,   const float* __restrict__ xz,
    const float* __restrict__ A_log,const float* __restrict__ Dp,
    float* __restrict__ yout)
{
    __shared__ float su [TTILE][128];
    __shared__ float sdt[TTILE][128];
    __shared__ float sz [TTILE][128];
    __shared__ float sBC[TTILE][32];

    const int bx  = blockIdx.x;
    const int dir = bx >> 6;
    const int b   = (bx >> 3) & 7;
    const int dch = bx & 7;
    const int tid = threadIdx.x;
    const int d   = dch*128 + tid;

    float a[NSTATE], h[NSTATE];
    bool fast = true;
#pragma unroll
    for (int n=0;n<NSTATE;n++){
        a[n] = -expf(A_log[(size_t)d*NSTATE + n]);
        h[n] = 0.f;
    }
#pragma unroll
    for (int n=1;n<NSTATE;n++){
        fast = fast && (fabsf(a[n] - a[0]*(float)(n+1)) <= 1e-4f*fabsf(a[n]));
    }
    const float a0 = a[0];
    const float Dv = Dp[d];

    const size_t cb = (size_t)dir*NT*DI + (size_t)(b*LL)*DI + d;
    const float* xcp = xc + cb;
    const float* dtp = dt + cb;
    float*       yp  = yout + cb;
    const float* xdp = xdbl + ((size_t)dir*NT + (size_t)b*LL)*64 + 32;
    const float* zp  = xz + (size_t)(b*LL)*(2*DI) + DI + d;

    const int bcrow = tid >> 3, bccq = tid & 7;

    for (int t0=0; t0<LL; t0+=TTILE){
        __syncthreads();
#pragma unroll
        for (int i=0;i<TTILE;i++){
            const int t = t0 + i;
            su [i][tid] = xcp[(size_t)t*DI];
            sdt[i][tid] = dtp[(size_t)t*DI];
            const int zt = dir ? (LL-1-t) : t;
            sz [i][tid] = zp[(size_t)zt*(2*DI)];
        }
        {
            float4 v = *reinterpret_cast<const float4*>(xdp + (size_t)(t0+bcrow)*64 + bccq*4);
            sBC[bcrow][bccq*4+0]=v.x; sBC[bcrow][bccq*4+1]=v.y;
            sBC[bcrow][bccq*4+2]=v.z; sBC[bcrow][bccq*4+3]=v.w;
        }
        __syncthreads();
        if (fast){
#pragma unroll
            for (int i=0;i<TTILE;i++){
                const float u   = su [i][tid];
                const float dtv = sdt[i][tid];
                const float dtu = dtv * u;
                const float r   = __expf(dtv * a0);
                float p = 1.f;
                float y = u * Dv;
#pragma unroll
                for (int n=0;n<NSTATE;n++){
                    p *= r;
                    h[n] = p*h[n] + dtu * sBC[i][n];
                    y   += h[n] * sBC[i][16+n];
                }
                y *= silu_fast(sz[i][tid]);
                yp[(size_t)(t0+i)*DI] = y;
            }
        } else {
#pragma unroll
            for (int i=0;i<TTILE;i++){
                const float u   = su [i][tid];
                const float dtv = sdt[i][tid];
                const float dtu = dtv * u;
                float y = u * Dv;
#pragma unroll
                for (int n=0;n<NSTATE;n++){
                    const float dA = __expf(dtv * a[n]);
                    h[n] = dA*h[n] + dtu * sBC[i][n];
                    y   += h[n] * sBC[i][16+n];
                }
                y *= silu_fast(sz[i][tid]);
                yp[(size_t)(t0+i)*DI] = y;
            }
        }
    }
}

// ---------------------------------------------------------------------------
// hidden[b,t,:] = o_fwd[b,t,:] + o_bwd[b,L-1-t,:]
// ---------------------------------------------------------------------------
__global__ void __launch_bounds__(256) add_kernel(
    const float* __restrict__ o, float* __restrict__ dst)
{
    const int flat = blockIdx.x*256 + threadIdx.x;
    const int e = flat & (DM-1);
    const int t = (flat >> 9) & (LL-1);
    const int b = flat >> 19;
    const int tok  = b*LL + t;
    const int tokb = b*LL + (LL-1-t);
    dst[flat] = o[(size_t)tok*DM + e] + o[(size_t)(NT + tokb)*DM + e];
}

// ---------------------------------------------------------------------------
// Launch
// ---------------------------------------------------------------------------
extern "C" void kernel_launch(void* const* d_in, const int* in_sizes, int n_in,
                              void* d_out, int out_size)
{
    (void)in_sizes; (void)n_in; (void)out_size;
    const float* x      = (const float*)d_in[0];
    const float* norm_w = (const float*)d_in[1];
    const float* norm_b = (const float*)d_in[2];
    const float* in_w   = (const float*)d_in[3];
    const float* conv_w = (const float*)d_in[4];
    const float* conv_b = (const float*)d_in[5];
    const float* xp_w   = (const float*)d_in[6];
    const float* dtp_w  = (const float*)d_in[7];
    const float* dtp_b  = (const float*)d_in[8];
    const float* A_log  = (const float*)d_in[9];
    const float* Dp     = (const float*)d_in[10];
    const float* out_w  = (const float*)d_in[11];
    float* dout = (float*)d_out;

    float *resid,*hid,*hbuf,*xz,*xc,*xdbl,*dtb,*yb,*ob;
    cudaGetSymbolAddress((void**)&resid, g_resid);
    cudaGetSymbolAddress((void**)&hid,   g_hid);
    cudaGetSymbolAddress((void**)&hbuf,  g_h);
    cudaGetSymbolAddress((void**)&xz,    g_xz);
    cudaGetSymbolAddress((void**)&xc,    g_xc);
    cudaGetSymbolAddress((void**)&xdbl,  g_xdbl);
    cudaGetSymbolAddress((void**)&dtb,   g_dt);
    cudaGetSymbolAddress((void**)&yb,    g_y);
    cudaGetSymbolAddress((void**)&ob,    g_o);

    for (int i=0;i<DEPTH;i++){
        ln_kernel<<<NT,128>>>( (i==0)? x : resid, (i==0)? (const float*)nullptr : hid,
                               resid, norm_w + i*DM, norm_b + i*DM, hbuf );

        // GEMM1: xz[8192,2048] = h @ in_w^T   (mma.sync split-bf16)
        gemm_mma_kernel<128><<<dim3(2048/128, 8192/128), 256>>>(
            hbuf, DM, in_w + (size_t)i*2*DI*DM, DM, xz, 2*DI);

        conv_kernel<<<(2*NT*DI)/256,256>>>(xz, conv_w + i*DI*4, conv_b + i*DI, xc);

        // GEMM2: xdbl[16384,64] = xc @ xp_w^T
        gemm_mma_kernel<64><<<dim3(1, 16384/128), 256>>>(
            xc, DI, xp_w + (size_t)i*64*DI, DI, xdbl, 64);

        // GEMM3: dt = softplus(xdbl[:, :32] @ dtp_w^T + dtp_b)   (SIMT, K=32)
        gemm_kernel<128,128,16,8,8,1><<<dim3(1024/128, 16384/128),256>>>(
            xdbl, 64, dtp_w + (size_t)i*DI*RK, dtp_b + i*DI, dtb, DI, RK);

        scan_kernel<<<128,128>>>(xc, xdbl, dtb, xz,
                                 A_log + (size_t)i*DI*NSTATE, Dp + i*DI, yb);

        // GEMM4: o[16384,512] = y @ out_w^T
        gemm_mma_kernel<128><<<dim3(512/128, 16384/128), 256>>>(
            yb, DI, out_w + (size_t)i*DM*DI, DI, ob, DM);

        add_kernel<<<(NT*DM)/256,256>>>(ob, (i==DEPTH-1)? dout : hid);
    }
}